// round 8
// baseline (speedup 1.0000x reference)
#include <cuda_runtime.h>
#include <cuda_bf16.h>

// AUCLoss via BIVARIATE Chebyshev separation (single data pass, no softplus
// in the main loop):
//   S = sum_pos sum_neg pw*nw*softplus(n-p) ~= sum_{m,k} a_mk P_m N_k
//   P_m = sum_pos pw T_m(p/5),  N_k = sum_neg nw T_k(n/5)
//   a_mk = 2D-DCT of softplus(x_r - x_q) at 25x25 Lobatto nodes (data-free,
//          computed by the finalize block; ~0.3us)
// rho = pi/5 + sqrt(1+(pi/5)^2) ~ 1.81 -> rho^-24 ~ 6e-7 per direction.
// B=64, C=206, N=13184, MARGIN=1.

#define NTOT    13184
#define NCLS    206
#define M_CHEB  24
#define NQ      25
#define NQ2     (NQ * NQ)        // 625
#define HALF    5.0f
#define TPB     256
#define GRID    52               // 52*256 = 13312 >= NTOT, one wave

// cos(pi * t / 24), t = 0..24 (float-exact literals; pure math constants)
__constant__ float c_cos25[NQ] = {
     1.00000000f,  0.99144486f,  0.96592583f,  0.92387953f,
     0.86602540f,  0.79335334f,  0.70710678f,  0.60876143f,
     0.50000000f,  0.38268343f,  0.25881905f,  0.13052619f,
     0.00000000f, -0.13052619f, -0.25881905f, -0.38268343f,
    -0.50000000f, -0.60876143f, -0.70710678f, -0.79335334f,
    -0.86602540f, -0.92387953f, -0.96592583f, -0.99144486f,
    -1.00000000f
};

// cos(pi * t / 24) for t in [0, 48)
__device__ __forceinline__ float cheb_cos(int t) {
    return c_cos25[(t <= M_CHEB) ? t : (2 * M_CHEB - t)];
}

// Device scratch (no allocation allowed)
__device__ float g_P[NQ][GRID];
__device__ float g_N[NQ][GRID];
__device__ float g_cnt[GRID];
__device__ int   g_ticket;

__device__ __forceinline__ float softplus_f(float d) {
    return fmaxf(d, 0.0f) + __logf(1.0f + __expf(-fabsf(d)));
}

__global__ void __launch_bounds__(TPB, 1)
fused_k(const float* __restrict__ preds,
        const float* __restrict__ sw,
        const int*   __restrict__ labels,
        float* __restrict__ out) {
    const int tid  = threadIdx.x;
    const int lane = tid & 31;
    const int wid  = tid >> 5;
    const int b    = blockIdx.x;
    const int idx  = b * TPB + tid;

    // ---------------- main pass: per-element Chebyshev moments --------------
    float pw = 0.0f, nw = 0.0f, u = 0.0f, cnt = 0.0f;
    if (idx < NTOT) {
        const float p   = preds[idx];
        const int   lab = labels[idx];
        const float w   = sw[idx / NCLS];
        pw  = (lab == 1) ? w : 0.0f;
        nw  = (lab == 0) ? w : 0.0f;
        cnt = (lab == 1) ? 1.0f : 0.0f;
        u   = fminf(1.0f, fmaxf(-1.0f, p * (1.0f / HALF)));
    }

    float pv[NQ], nv[NQ];
    {
        const float u2 = 2.0f * u;
        float t0 = 1.0f, t1 = u;
        pv[0] = pw;      nv[0] = nw;
        pv[1] = pw * u;  nv[1] = nw * u;
        #pragma unroll
        for (int m = 2; m < NQ; m++) {
            const float t = fmaf(u2, t1, -t0);
            pv[m] = pw * t;
            nv[m] = nw * t;
            t0 = t1; t1 = t;
        }
    }

    // ---------------- block reduction of 51 values --------------------------
    __shared__ float smP[NQ][8], smN[NQ][8], smC[8];
    #pragma unroll
    for (int m = 0; m < NQ; m++) {
        float a = pv[m], c = nv[m];
        #pragma unroll
        for (int o = 16; o; o >>= 1) {
            a += __shfl_xor_sync(0xFFFFFFFFu, a, o);
            c += __shfl_xor_sync(0xFFFFFFFFu, c, o);
        }
        if (lane == 0) { smP[m][wid] = a; smN[m][wid] = c; }
    }
    {
        float c = cnt;
        #pragma unroll
        for (int o = 16; o; o >>= 1) c += __shfl_xor_sync(0xFFFFFFFFu, c, o);
        if (lane == 0) smC[wid] = c;
    }
    __syncthreads();
    if (tid < NQ) {
        const float r = ((smP[tid][0] + smP[tid][1]) + (smP[tid][2] + smP[tid][3]))
                      + ((smP[tid][4] + smP[tid][5]) + (smP[tid][6] + smP[tid][7]));
        g_P[tid][b] = r;
    } else if (tid >= 32 && tid < 32 + NQ) {
        const int m = tid - 32;
        const float r = ((smN[m][0] + smN[m][1]) + (smN[m][2] + smN[m][3]))
                      + ((smN[m][4] + smN[m][5]) + (smN[m][6] + smN[m][7]));
        g_N[m][b] = r;
    } else if (tid == 64) {
        g_cnt[b] = ((smC[0] + smC[1]) + (smC[2] + smC[3]))
                 + ((smC[4] + smC[5]) + (smC[6] + smC[7]));
    }

    // ---------------- ticket: last-arriving block finalizes -----------------
    __shared__ int s_last;
    __syncthreads();
    if (tid == 0) {
        __threadfence();
        s_last = (atomicAdd(&g_ticket, 1) == GRID - 1) ? 1 : 0;
    }
    __syncthreads();
    if (!s_last) return;
    __threadfence();

    __shared__ float sP[NQ], sN[NQ], sCnt;
    __shared__ float sF[NQ2];     // softplus at node grid, then reused
    __shared__ float sG[NQ2];     // stage-1 DCT
    __shared__ float swred[8];

    if (tid < NQ) {
        float a0 = 0.0f, a1 = 0.0f, a2 = 0.0f, a3 = 0.0f;
        #pragma unroll
        for (int k = 0; k < GRID; k += 4) {
            a0 += __ldcg(&g_P[tid][k + 0]);
            a1 += __ldcg(&g_P[tid][k + 1]);
            a2 += __ldcg(&g_P[tid][k + 2]);
            a3 += __ldcg(&g_P[tid][k + 3]);
        }
        sP[tid] = (a0 + a1) + (a2 + a3);
    } else if (tid >= 32 && tid < 32 + NQ) {
        const int m = tid - 32;
        float a0 = 0.0f, a1 = 0.0f, a2 = 0.0f, a3 = 0.0f;
        #pragma unroll
        for (int k = 0; k < GRID; k += 4) {
            a0 += __ldcg(&g_N[m][k + 0]);
            a1 += __ldcg(&g_N[m][k + 1]);
            a2 += __ldcg(&g_N[m][k + 2]);
            a3 += __ldcg(&g_N[m][k + 3]);
        }
        sN[m] = (a0 + a1) + (a2 + a3);
    } else if (tid == 64) {
        float a = 0.0f;
        #pragma unroll
        for (int k = 0; k < GRID; k++) a += __ldcg(&g_cnt[k]);
        sCnt = a;
    }

    // node-grid softplus values: F[q][r] = softplus(x_r - x_q), x = HALF*cos
    for (int i = tid; i < NQ2; i += TPB) {
        const int q = i / NQ, r = i % NQ;
        sF[i] = softplus_f(HALF * (c_cos25[r] - c_cos25[q]));
    }
    __syncthreads();

    // stage 1: G[m][r] = (2/M) * wm * sum''_q F[q][r] cos(pi m q / M)
    for (int i = tid; i < NQ2; i += TPB) {
        const int m = i / NQ, r = i % NQ;
        float s = 0.5f * sF[r];                        // q = 0 (weight 1/2)
        #pragma unroll
        for (int q = 1; q < M_CHEB; q++)
            s = fmaf(sF[q * NQ + r], cheb_cos((m * q) % (2 * M_CHEB)), s);
        s = fmaf(0.5f * sF[M_CHEB * NQ + r], cheb_cos((m * M_CHEB) % (2 * M_CHEB)), s);
        s *= (2.0f / (float)M_CHEB);
        if (m == 0 || m == M_CHEB) s *= 0.5f;
        sG[i] = s;
    }
    __syncthreads();

    // stage 2 fused with the dot product:
    // a_mk = (2/M) * wk * sum''_r G[m][r] cos(pi k r / M);  acc += a_mk*P_m*N_k
    float acc = 0.0f;
    for (int i = tid; i < NQ2; i += TPB) {
        const int m = i / NQ, k = i % NQ;
        float s = 0.5f * sG[m * NQ];                   // r = 0
        #pragma unroll
        for (int r = 1; r < M_CHEB; r++)
            s = fmaf(sG[m * NQ + r], cheb_cos((k * r) % (2 * M_CHEB)), s);
        s = fmaf(0.5f * sG[m * NQ + M_CHEB], cheb_cos((k * M_CHEB) % (2 * M_CHEB)), s);
        s *= (2.0f / (float)M_CHEB);
        if (k == 0 || k == M_CHEB) s *= 0.5f;
        acc = fmaf(s, sP[m] * sN[k], acc);
    }
    #pragma unroll
    for (int o = 16; o; o >>= 1) acc += __shfl_xor_sync(0xFFFFFFFFu, acc, o);
    if (lane == 0) swred[wid] = acc;
    __syncthreads();
    if (tid == 0) {
        const float S = ((swred[0] + swred[1]) + (swred[2] + swred[3]))
                      + ((swred[4] + swred[5]) + (swred[6] + swred[7]));
        const float npos = sCnt;
        const float nneg = (float)NTOT - sCnt;
        out[0] = S / (npos * nneg);
        g_ticket = 0;   // replay-safe reset: every block already incremented
    }
}

extern "C" void kernel_launch(void* const* d_in, const int* in_sizes, int n_in,
                              void* d_out, int out_size) {
    const float* preds  = (const float*)d_in[0];
    const float* sw     = (const float*)d_in[1];
    const int*   labels = (const int*)d_in[2];
    fused_k<<<GRID, TPB>>>(preds, sw, labels, (float*)d_out);
}

// round 10
// speedup vs baseline: 1.8789x; 1.8789x over previous
#include <cuda_runtime.h>
#include <cuda_bf16.h>

// AUCLoss via bivariate Chebyshev separation, cardinal (node-space) finalize.
//   S = sum_pos sum_neg pw*nw*softplus(n-p)
//   P_m = sum_pos pw T_m(p/5),  N_k = sum_neg nw T_k(n/5)   (one data pass)
//   LP_q = (2/M) w_q sum''_m cos(pi m q/M) P_m              (node-space xform)
//   LN_r likewise;  S = sum_{q,r} LP_q LN_r softplus(x_r - x_q)
// rho = pi/5 + sqrt(1+(pi/5)^2) ~ 1.81 -> rho^-24 ~ 6e-7 per direction.
// B=64, C=206, N=13184, MARGIN=1.

#define NTOT    13184
#define NCLS    206
#define M_CHEB  24
#define NQ      25
#define NQ2     (NQ * NQ)        // 625
#define HALF    5.0f
#define TPB     256
#define GRID    52               // 52*256 = 13312 >= NTOT, one wave

// cos(pi * t / 24), t = 0..24 (float-exact literals; pure math constants)
__constant__ float c_cos25[NQ] = {
     1.00000000f,  0.99144486f,  0.96592583f,  0.92387953f,
     0.86602540f,  0.79335334f,  0.70710678f,  0.60876143f,
     0.50000000f,  0.38268343f,  0.25881905f,  0.13052619f,
     0.00000000f, -0.13052619f, -0.25881905f, -0.38268343f,
    -0.50000000f, -0.60876143f, -0.70710678f, -0.79335334f,
    -0.86602540f, -0.92387953f, -0.96592583f, -0.99144486f,
    -1.00000000f
};

// Device scratch (no allocation allowed)
__device__ float g_P[NQ][GRID];
__device__ float g_N[NQ][GRID];
__device__ float g_cnt[GRID];
__device__ int   g_ticket;

__device__ __forceinline__ float softplus_f(float d) {
    return fmaxf(d, 0.0f) + __logf(1.0f + __expf(-fabsf(d)));
}

__global__ void __launch_bounds__(TPB, 1)
fused_k(const float* __restrict__ preds,
        const float* __restrict__ sw,
        const int*   __restrict__ labels,
        float* __restrict__ out) {
    const int tid  = threadIdx.x;
    const int lane = tid & 31;
    const int wid  = tid >> 5;
    const int b    = blockIdx.x;
    const int idx  = b * TPB + tid;

    // ---------------- main pass: per-element Chebyshev moments --------------
    float pw = 0.0f, nw = 0.0f, u = 0.0f, cnt = 0.0f;
    if (idx < NTOT) {
        const float p   = preds[idx];
        const int   lab = labels[idx];
        const float w   = sw[idx / NCLS];
        pw  = (lab == 1) ? w : 0.0f;
        nw  = (lab == 0) ? w : 0.0f;
        cnt = (lab == 1) ? 1.0f : 0.0f;
        u   = fminf(1.0f, fmaxf(-1.0f, p * (1.0f / HALF)));
    }

    float pv[NQ], nv[NQ];
    {
        const float u2 = 2.0f * u;
        float t0 = 1.0f, t1 = u;
        pv[0] = pw;      nv[0] = nw;
        pv[1] = pw * u;  nv[1] = nw * u;
        #pragma unroll
        for (int m = 2; m < NQ; m++) {
            const float t = fmaf(u2, t1, -t0);
            pv[m] = pw * t;
            nv[m] = nw * t;
            t0 = t1; t1 = t;
        }
    }

    // ---------------- block reduction of 51 values --------------------------
    __shared__ float smP[NQ][8], smN[NQ][8], smC[8];
    #pragma unroll
    for (int m = 0; m < NQ; m++) {
        float a = pv[m], c = nv[m];
        #pragma unroll
        for (int o = 16; o; o >>= 1) {
            a += __shfl_xor_sync(0xFFFFFFFFu, a, o);
            c += __shfl_xor_sync(0xFFFFFFFFu, c, o);
        }
        if (lane == 0) { smP[m][wid] = a; smN[m][wid] = c; }
    }
    {
        float c = cnt;
        #pragma unroll
        for (int o = 16; o; o >>= 1) c += __shfl_xor_sync(0xFFFFFFFFu, c, o);
        if (lane == 0) smC[wid] = c;
    }
    __syncthreads();
    if (tid < NQ) {
        const float r = ((smP[tid][0] + smP[tid][1]) + (smP[tid][2] + smP[tid][3]))
                      + ((smP[tid][4] + smP[tid][5]) + (smP[tid][6] + smP[tid][7]));
        g_P[tid][b] = r;
    } else if (tid >= 32 && tid < 32 + NQ) {
        const int m = tid - 32;
        const float r = ((smN[m][0] + smN[m][1]) + (smN[m][2] + smN[m][3]))
                      + ((smN[m][4] + smN[m][5]) + (smN[m][6] + smN[m][7]));
        g_N[m][b] = r;
    } else if (tid == 64) {
        g_cnt[b] = ((smC[0] + smC[1]) + (smC[2] + smC[3]))
                 + ((smC[4] + smC[5]) + (smC[6] + smC[7]));
    }

    // ---------------- ticket: last-arriving block finalizes -----------------
    __shared__ int s_last;
    __syncthreads();
    if (tid == 0) {
        __threadfence();
        s_last = (atomicAdd(&g_ticket, 1) == GRID - 1) ? 1 : 0;
    }
    __syncthreads();
    if (!s_last) return;
    __threadfence();

    __shared__ float sct[2 * M_CHEB];   // cos(pi t/24), t in [0,48) - SMEM table
    __shared__ float sx[NQ];            // node values HALF*cos
    __shared__ float spart[2 * NQ][4];  // quarter-row partial sums (P rows 0..24, N rows 25..49)
    __shared__ float sLP[NQ], sLN[NQ], sCnt;
    __shared__ float swred[8];

    // build smem tables
    if (tid < 2 * M_CHEB) {
        const int t = tid;
        sct[t] = c_cos25[(t <= M_CHEB) ? t : (2 * M_CHEB - t)];
    }
    if (tid >= 64 && tid < 64 + NQ) sx[tid - 64] = HALF * c_cos25[tid - 64];
    if (tid == 96) {
        float a = 0.0f;
        #pragma unroll
        for (int k = 0; k < GRID; k++) a += __ldcg(&g_cnt[k]);
        sCnt = a;
    }

    // parallel gather of per-block partials: 50 rows x 4 quarter-sums
    if (tid < 200) {
        const int row = tid >> 2;            // 0..49
        const int qu  = tid & 3;             // 0..3
        const float* src = (row < NQ) ? &g_P[row][0] : &g_N[row - NQ][0];
        const int base = qu * 13;
        float a = 0.0f;
        #pragma unroll
        for (int k = 0; k < 13; k++) a += __ldcg(&src[base + k]);
        spart[row][qu] = a;
    }
    __syncthreads();

    // node-space transform: LP_q, LN_q (50 threads, 25-term loops, smem table)
    if (tid < 2 * NQ) {
        const int q     = (tid < NQ) ? tid : (tid - NQ);
        const int rbase = (tid < NQ) ? 0 : NQ;
        // row sums P_m (or N_m) from quarter partials
        float s = 0.0f;
        {
            const float* pr0 = &spart[rbase][0];
            // m = 0 term (weight 1/2): cos(0)=1
            const float m0 = (pr0[0] + pr0[1]) + (pr0[2] + pr0[3]);
            s = 0.5f * m0;
        }
        #pragma unroll
        for (int m = 1; m < M_CHEB; m++) {
            const float* pr = &spart[rbase + m][0];
            const float Pm = (pr[0] + pr[1]) + (pr[2] + pr[3]);
            s = fmaf(Pm, sct[(m * q) % (2 * M_CHEB)], s);
        }
        {
            const float* pr = &spart[rbase + M_CHEB][0];
            const float PM = (pr[0] + pr[1]) + (pr[2] + pr[3]);
            s = fmaf(0.5f * PM, sct[(M_CHEB * q) % (2 * M_CHEB)], s);
        }
        s *= (2.0f / (float)M_CHEB);
        if (q == 0 || q == M_CHEB) s *= 0.5f;
        if (tid < NQ) sLP[q] = s; else sLN[q] = s;
    }
    __syncthreads();

    // S = sum_{q,r} LP_q * LN_r * softplus(x_r - x_q)   (625 terms)
    float acc = 0.0f;
    for (int i = tid; i < NQ2; i += TPB) {
        const int q = i / NQ, r = i % NQ;
        acc = fmaf(sLP[q] * sLN[r], softplus_f(sx[r] - sx[q]), acc);
    }
    #pragma unroll
    for (int o = 16; o; o >>= 1) acc += __shfl_xor_sync(0xFFFFFFFFu, acc, o);
    if (lane == 0) swred[wid] = acc;
    __syncthreads();
    if (tid == 0) {
        const float S = ((swred[0] + swred[1]) + (swred[2] + swred[3]))
                      + ((swred[4] + swred[5]) + (swred[6] + swred[7]));
        const float npos = sCnt;
        const float nneg = (float)NTOT - sCnt;
        out[0] = S / (npos * nneg);
        g_ticket = 0;   // replay-safe reset: every block already incremented
    }
}

extern "C" void kernel_launch(void* const* d_in, const int* in_sizes, int n_in,
                              void* d_out, int out_size) {
    const float* preds  = (const float*)d_in[0];
    const float* sw     = (const float*)d_in[1];
    const int*   labels = (const int*)d_in[2];
    fused_k<<<GRID, TPB>>>(preds, sw, labels, (float*)d_out);
}